// round 10
// baseline (speedup 1.0000x reference)
#include <cuda_runtime.h>
#include <cstdint>

#define BATCH 32
#define CCH   256
#define HW    1024
#define TM 128
#define TN 128
#define KT 16
#define RS 136                        // smem row stride (words): conflict-free
// stage layout (word offsets)
#define W_AH  0                       // 16x136 fp32
#define W_BH  2176                    // 16x136 fp32
#define W_AHB 4352                    // 8x136 u32 (bf16 pair)
#define W_ALB 5440
#define W_BHB 6528
#define W_BLB 7616
#define STAGEW 8704
#define SMEM_DYN (2 * STAGEW * 4)
#define INV_T 14.285714285714286f

__device__ float    g_Ah [(size_t)BATCH * CCH * HW];
__device__ float    g_Bh [(size_t)BATCH * CCH * HW];
__device__ unsigned g_Ahb[(size_t)BATCH * (CCH / 2) * HW];
__device__ unsigned g_Alb[(size_t)BATCH * (CCH / 2) * HW];
__device__ unsigned g_Bhb[(size_t)BATCH * (CCH / 2) * HW];
__device__ unsigned g_Blb[(size_t)BATCH * (CCH / 2) * HW];
__device__ float    g_M  [(size_t)BATCH * HW * HW];
__device__ unsigned g_maxIk[BATCH * HW];
__device__ unsigned g_maxJk[BATCH * HW];
__device__ float    g_sumI[BATCH * HW];
__device__ float    g_sumJ[BATCH * HW];

__device__ __forceinline__ unsigned fkey(float f) {
    unsigned u = __float_as_uint(f);
    return u ^ ((unsigned)(((int)u) >> 31) | 0x80000000u);
}
__device__ __forceinline__ float kdec(unsigned k) {
    unsigned u = (k & 0x80000000u) ? (k ^ 0x80000000u) : ~k;
    return __uint_as_float(u);
}
__device__ __forceinline__ uint32_t smem_u32(const void* p) {
    uint32_t a;
    asm("{ .reg .u64 t; cvta.to.shared.u64 t, %1; cvt.u32.u64 %0, t; }" : "=r"(a) : "l"(p));
    return a;
}
__device__ __forceinline__ void tf32_hi(float v, float& hi) {
    uint32_t hv; asm("cvt.rna.tf32.f32 %0, %1;" : "=r"(hv) : "f"(v));
    hi = __uint_as_float(hv);
}
// pack (lo_half = e, hi_half = o) as bf16x2
__device__ __forceinline__ unsigned bfpack(float e, float o) {
    unsigned r;
    asm("cvt.rn.bf16x2.f32 %0, %1, %2;" : "=r"(r) : "f"(o), "f"(e));
    return r;
}
__device__ __forceinline__ void cp16(uint32_t dst, const void* src) {
    asm volatile("cp.async.cg.shared.global [%0], [%1], 16;" :: "r"(dst), "l"(src));
}
#define CP_COMMIT() asm volatile("cp.async.commit_group;" ::: "memory")
#define CP_WAIT1()  asm volatile("cp.async.wait_group 1;" ::: "memory")

__device__ __forceinline__ void mma8(float* c, const unsigned* a, const unsigned* b) {
    asm volatile(
        "mma.sync.aligned.m16n8k8.row.col.f32.tf32.tf32.f32 "
        "{%0,%1,%2,%3}, {%4,%5,%6,%7}, {%8,%9}, {%0,%1,%2,%3};"
        : "+f"(c[0]), "+f"(c[1]), "+f"(c[2]), "+f"(c[3])
        : "r"(a[0]), "r"(a[1]), "r"(a[2]), "r"(a[3]), "r"(b[0]), "r"(b[1]));
}
__device__ __forceinline__ void mma16bf(float* c, const unsigned* a, const unsigned* b) {
    asm volatile(
        "mma.sync.aligned.m16n8k16.row.col.f32.bf16.bf16.f32 "
        "{%0,%1,%2,%3}, {%4,%5,%6,%7}, {%8,%9}, {%0,%1,%2,%3};"
        : "+f"(c[0]), "+f"(c[1]), "+f"(c[2]), "+f"(c[3])
        : "r"(a[0]), "r"(a[1]), "r"(a[2]), "r"(a[3]), "r"(b[0]), "r"(b[1]));
}

// ---------------- K0: reset ----------------
__global__ void k_init() {
    int idx = blockIdx.x * blockDim.x + threadIdx.x;
    if (idx < BATCH * HW) {
        g_maxIk[idx] = 0u;
        g_maxJk[idx] = 0u;
        g_sumI[idx]  = 0.f;
    }
}

// ---------------- K1: A prep — transpose (h,w)->(j=w*32+h), split, pack --------
__global__ __launch_bounds__(256) void k_prepA(const float* __restrict__ A) {
    __shared__ float s0[32][33], s1[32][33];
    const int bc = blockIdx.x;                 // b*128 + cp
    const int b = bc >> 7, cp = bc & 127;
    const int c0 = 2 * cp;
    const float* Ap0 = A + ((size_t)b * CCH + c0) * 1024;
    const float* Ap1 = Ap0 + 1024;
    float* Oh0 = g_Ah + ((size_t)b * CCH + c0) * 1024;
    float* Oh1 = Oh0 + 1024;
    unsigned* Ohb = g_Ahb + ((size_t)b * (CCH / 2) + cp) * 1024;
    unsigned* Olb = g_Alb + ((size_t)b * (CCH / 2) + cp) * 1024;
    const int t = threadIdx.x;
#pragma unroll
    for (int l = 0; l < 4; l++) {
        int idx = t + l * 256;
        s0[idx >> 5][idx & 31] = Ap0[idx];
        s1[idx >> 5][idx & 31] = Ap1[idx];
    }
    __syncthreads();
#pragma unroll
    for (int l = 0; l < 4; l++) {
        int idx = t + l * 256;
        float v0 = s0[idx & 31][idx >> 5];
        float v1 = s1[idx & 31][idx >> 5];
        float h0, h1; tf32_hi(v0, h0); tf32_hi(v1, h1);
        Oh0[idx] = h0; Oh1[idx] = h1;
        Ohb[idx] = bfpack(h0, h1);
        Olb[idx] = bfpack(v0 - h0, v1 - h1);
    }
}

// ---------------- K2: B prep — split + pack (no transpose) ----------------
__global__ __launch_bounds__(256) void k_prepB(const float* __restrict__ B) {
    const int i = blockIdx.x * 256 + threadIdx.x;
    const int cp = blockIdx.y, b = blockIdx.z;
    const size_t base = ((size_t)b * CCH + 2 * cp) * 1024;
    float v0 = B[base + i];
    float v1 = B[base + 1024 + i];
    float h0, h1; tf32_hi(v0, h0); tf32_hi(v1, h1);
    g_Bh[base + i] = h0;
    g_Bh[base + 1024 + i] = h1;
    const size_t pbase = ((size_t)b * (CCH / 2) + cp) * 1024;
    g_Bhb[pbase + i] = bfpack(h0, h1);
    g_Blb[pbase + i] = bfpack(v0 - h0, v1 - h1);
}

// ---------------- K3: GEMM — tf32 main + bf16 corrections + tile maxes --------
__device__ __forceinline__ void fill_buf(uint32_t buf, int k0,
        const float* pAh, const float* pBh,
        const unsigned* pAhb, const unsigned* pAlb,
        const unsigned* pBhb, const unsigned* pBlb, int t) {
#pragma unroll
    for (int l = 0; l < 2; l++) {
        int id = t + 256 * l;
        int r = id >> 5, c4 = id & 31;
        uint32_t so = (uint32_t)(r * RS + c4 * 4) * 4u;
        size_t go = (size_t)(k0 + r) * HW + c4 * 4;
        cp16(buf + W_AH * 4 + so, pAh + go);
        cp16(buf + W_BH * 4 + so, pBh + go);
    }
    {
        int r = t >> 5, c4 = t & 31;
        uint32_t so = (uint32_t)(r * RS + c4 * 4) * 4u;
        size_t go = (size_t)(k0 / 2 + r) * HW + c4 * 4;
        cp16(buf + W_AHB * 4 + so, pAhb + go);
        cp16(buf + W_ALB * 4 + so, pAlb + go);
        cp16(buf + W_BHB * 4 + so, pBhb + go);
        cp16(buf + W_BLB * 4 + so, pBlb + go);
    }
}

__global__ __launch_bounds__(256, 2) void k_gemm_mma() {
    extern __shared__ float dsm[];
    __shared__ unsigned rowk[TM], colk[TN];
    const uint32_t sb = smem_u32(dsm);

    const int t = threadIdx.x;
    const int b = blockIdx.z, i0 = blockIdx.x * TN, j0 = blockIdx.y * TM;
    const int wid = t >> 5, lane = t & 31;
    const int wm = wid >> 1, wn = wid & 1;
    const int g = lane >> 2, tig = lane & 3;

    if (t < TM) rowk[t] = 0u;
    if (t < TN) colk[t] = 0u;

    const float*    pAh  = g_Ah  + (size_t)b * CCH * HW + j0;
    const float*    pBh  = g_Bh  + (size_t)b * CCH * HW + i0;
    const unsigned* pAhb = g_Ahb + (size_t)b * (CCH / 2) * HW + j0;
    const unsigned* pAlb = g_Alb + (size_t)b * (CCH / 2) * HW + j0;
    const unsigned* pBhb = g_Bhb + (size_t)b * (CCH / 2) * HW + i0;
    const unsigned* pBlb = g_Blb + (size_t)b * (CCH / 2) * HW + i0;

    float c[2][8][4];
#pragma unroll
    for (int mt = 0; mt < 2; mt++)
#pragma unroll
        for (int nt = 0; nt < 8; nt++)
#pragma unroll
            for (int q = 0; q < 4; q++) c[mt][nt][q] = 0.f;

    fill_buf(sb, 0, pAh, pBh, pAhb, pAlb, pBhb, pBlb, t);
    CP_COMMIT();
    fill_buf(sb + STAGEW * 4, KT, pAh, pBh, pAhb, pAlb, pBhb, pBlb, t);
    CP_COMMIT();

    for (int k = 0; k < CCH / KT; k++) {
        const int p = k & 1;
        const float* s0 = dsm + (size_t)p * STAGEW;
        const float* sAh = s0 + W_AH;
        const float* sBh = s0 + W_BH;
        const unsigned* sAhb = (const unsigned*)(s0 + W_AHB);
        const unsigned* sAlb = (const unsigned*)(s0 + W_ALB);
        const unsigned* sBhb = (const unsigned*)(s0 + W_BHB);
        const unsigned* sBlb = (const unsigned*)(s0 + W_BLB);
        CP_WAIT1();
        __syncthreads();

        // ---- main product: tf32, two k8 steps ----
#pragma unroll
        for (int kk = 0; kk < KT; kk += 8) {
            unsigned ah[2][4], bh[8][2];
#pragma unroll
            for (int mt = 0; mt < 2; mt++) {
                const int m = wm * 32 + mt * 16 + g;
                ah[mt][0] = __float_as_uint(sAh[(kk + tig) * RS + m]);
                ah[mt][1] = __float_as_uint(sAh[(kk + tig) * RS + m + 8]);
                ah[mt][2] = __float_as_uint(sAh[(kk + tig + 4) * RS + m]);
                ah[mt][3] = __float_as_uint(sAh[(kk + tig + 4) * RS + m + 8]);
            }
#pragma unroll
            for (int nt = 0; nt < 8; nt++) {
                const int n = wn * 64 + nt * 8 + g;
                bh[nt][0] = __float_as_uint(sBh[(kk + tig) * RS + n]);
                bh[nt][1] = __float_as_uint(sBh[(kk + tig + 4) * RS + n]);
            }
#pragma unroll
            for (int mt = 0; mt < 2; mt++)
#pragma unroll
                for (int nt = 0; nt < 8; nt++) mma8(c[mt][nt], ah[mt], bh[nt]);
        }

        // ---- corrections: bf16 k16 (packed pairs), one step each ----
        {
            unsigned pa[2][4], pb[8][2];
#pragma unroll
            for (int mt = 0; mt < 2; mt++) {
                const int m = wm * 32 + mt * 16 + g;
                pa[mt][0] = sAhb[tig * RS + m];
                pa[mt][1] = sAhb[tig * RS + m + 8];
                pa[mt][2] = sAhb[(tig + 4) * RS + m];
                pa[mt][3] = sAhb[(tig + 4) * RS + m + 8];
            }
#pragma unroll
            for (int nt = 0; nt < 8; nt++) {
                const int n = wn * 64 + nt * 8 + g;
                pb[nt][0] = sBlb[tig * RS + n];
                pb[nt][1] = sBlb[(tig + 4) * RS + n];
            }
#pragma unroll
            for (int mt = 0; mt < 2; mt++)
#pragma unroll
                for (int nt = 0; nt < 8; nt++) mma16bf(c[mt][nt], pa[mt], pb[nt]);

#pragma unroll
            for (int mt = 0; mt < 2; mt++) {
                const int m = wm * 32 + mt * 16 + g;
                pa[mt][0] = sAlb[tig * RS + m];
                pa[mt][1] = sAlb[tig * RS + m + 8];
                pa[mt][2] = sAlb[(tig + 4) * RS + m];
                pa[mt][3] = sAlb[(tig + 4) * RS + m + 8];
            }
#pragma unroll
            for (int nt = 0; nt < 8; nt++) {
                const int n = wn * 64 + nt * 8 + g;
                pb[nt][0] = sBhb[tig * RS + n];
                pb[nt][1] = sBhb[(tig + 4) * RS + n];
            }
#pragma unroll
            for (int mt = 0; mt < 2; mt++)
#pragma unroll
                for (int nt = 0; nt < 8; nt++) mma16bf(c[mt][nt], pa[mt], pb[nt]);
        }

        __syncthreads();
        if (k + 2 < CCH / KT)
            fill_buf(sb + (uint32_t)p * STAGEW * 4, (k + 2) * KT,
                     pAh, pBh, pAhb, pAlb, pBhb, pBlb, t);
        CP_COMMIT();
    }

    // scale
#pragma unroll
    for (int mt = 0; mt < 2; mt++)
#pragma unroll
        for (int nt = 0; nt < 8; nt++)
#pragma unroll
            for (int q = 0; q < 4; q++) c[mt][nt][q] *= INV_T;

    // store G
#pragma unroll
    for (int mt = 0; mt < 2; mt++)
#pragma unroll
        for (int hb = 0; hb < 2; hb++) {
            const int j = j0 + wm * 32 + mt * 16 + g + 8 * hb;
            float* rowp = g_M + ((size_t)b * HW + j) * HW + i0 + wn * 64;
#pragma unroll
            for (int nt = 0; nt < 8; nt++)
                *(float2*)(rowp + nt * 8 + tig * 2) =
                    make_float2(c[mt][nt][2 * hb], c[mt][nt][2 * hb + 1]);
        }

    // row maxes
#pragma unroll
    for (int mt = 0; mt < 2; mt++)
#pragma unroll
        for (int hb = 0; hb < 2; hb++) {
            float m = -3.0e38f;
#pragma unroll
            for (int nt = 0; nt < 8; nt++)
                m = fmaxf(m, fmaxf(c[mt][nt][2 * hb], c[mt][nt][2 * hb + 1]));
#pragma unroll
            for (int o = 1; o < 4; o <<= 1)
                m = fmaxf(m, __shfl_xor_sync(0xffffffffu, m, o));
            if (tig == 0) atomicMax(&rowk[wm * 32 + mt * 16 + g + 8 * hb], fkey(m));
        }
    // col maxes
#pragma unroll
    for (int nt = 0; nt < 8; nt++)
#pragma unroll
        for (int par = 0; par < 2; par++) {
            float m = fmaxf(fmaxf(c[0][nt][par], c[0][nt][2 + par]),
                            fmaxf(c[1][nt][par], c[1][nt][2 + par]));
#pragma unroll
            for (int o = 4; o < 32; o <<= 1)
                m = fmaxf(m, __shfl_xor_sync(0xffffffffu, m, o));
            if (g == 0) atomicMax(&colk[wn * 64 + nt * 8 + tig * 2 + par], fkey(m));
        }
    __syncthreads();
    if (t < TM) atomicMax(&g_maxJk[b * HW + j0 + t], rowk[t]);
    if (t < TN) atomicMax(&g_maxIk[b * HW + i0 + t], colk[t]);
}

// ---------------- K4: stats + write unnormalized product to out ----------------
__global__ __launch_bounds__(256) void k_stats(float* __restrict__ out) {
    __shared__ float sI[8][1024];
    const int b = blockIdx.y, j0 = blockIdx.x * 128;
    const int t = threadIdx.x, w = t >> 5, lane = t & 31;

    float mIv[32], accI[32];
#pragma unroll
    for (int q = 0; q < 8; q++)
#pragma unroll
        for (int s = 0; s < 4; s++) {
            mIv[q * 4 + s] = kdec(g_maxIk[b * HW + q * 128 + lane * 4 + s]);
            accI[q * 4 + s] = 0.f;
        }

    for (int r = 0; r < 16; r++) {
        const int row = j0 + w + 8 * r;
        const float mJ = kdec(g_maxJk[b * HW + row]);
        const float* Gp = g_M + ((size_t)b * HW + row) * HW;
        float* Op = out + ((size_t)b * HW + row) * HW;
        float accJ = 0.f;
#pragma unroll
        for (int q = 0; q < 8; q++) {
            float4 v = *(const float4*)(Gp + q * 128 + lane * 4);
            float ex = __expf(v.x - mIv[q * 4 + 0]);
            float ey = __expf(v.y - mIv[q * 4 + 1]);
            float ez = __expf(v.z - mIv[q * 4 + 2]);
            float ew = __expf(v.w - mIv[q * 4 + 3]);
            float jx = __expf(v.x - mJ), jy = __expf(v.y - mJ);
            float jz = __expf(v.z - mJ), jw = __expf(v.w - mJ);
            accI[q * 4 + 0] += ex; accI[q * 4 + 1] += ey;
            accI[q * 4 + 2] += ez; accI[q * 4 + 3] += ew;
            accJ += jx + jy + jz + jw;
            *(float4*)(Op + q * 128 + lane * 4) =
                make_float4(ex * jx, ey * jy, ez * jz, ew * jw);
        }
#pragma unroll
        for (int o = 16; o > 0; o >>= 1) accJ += __shfl_xor_sync(0xffffffffu, accJ, o);
        if (lane == 0) g_sumJ[b * HW + row] = accJ;
    }
#pragma unroll
    for (int q = 0; q < 8; q++)
#pragma unroll
        for (int s = 0; s < 4; s++) sI[w][q * 128 + lane * 4 + s] = accI[q * 4 + s];
    __syncthreads();
#pragma unroll
    for (int col = t; col < 1024; col += 256) {
        float s = 0.f;
#pragma unroll
        for (int ww = 0; ww < 8; ww++) s += sI[ww][col];
        atomicAdd(&g_sumI[b * HW + col], s);
    }
}

// ---------------- K5: out *= rI * rJ (pure stream, no exp) ----------------
__global__ __launch_bounds__(256) void k_norm(float* __restrict__ out) {
    __shared__ float rIs[1024], rJs[128];
    const int b = blockIdx.y, j0 = blockIdx.x * 128;
    const int t = threadIdx.x;
#pragma unroll
    for (int i = t; i < 1024; i += 256) rIs[i] = 1.0f / g_sumI[b * HW + i];
    if (t < 128) rJs[t] = 1.0f / g_sumJ[b * HW + j0 + t];
    __syncthreads();
    float* Op = out + ((size_t)b * HW + j0) * HW;
#pragma unroll 2
    for (int idx = t; idx < 128 * 256; idx += 256) {
        const int jj = idx >> 8, i4 = (idx & 255) * 4;
        float4 v = *(float4*)(Op + (size_t)jj * HW + i4);
        const float rj = rJs[jj];
        v.x *= rIs[i4 + 0] * rj;
        v.y *= rIs[i4 + 1] * rj;
        v.z *= rIs[i4 + 2] * rj;
        v.w *= rIs[i4 + 3] * rj;
        *(float4*)(Op + (size_t)jj * HW + i4) = v;
    }
}

// ---------------- launch ----------------
extern "C" void kernel_launch(void* const* d_in, const int* in_sizes, int n_in,
                              void* d_out, int out_size) {
    const float* A  = (const float*)d_in[0];
    const float* Bf = (const float*)d_in[1];
    float* out = (float*)d_out;

    cudaFuncSetAttribute(k_gemm_mma, cudaFuncAttributeMaxDynamicSharedMemorySize, SMEM_DYN);

    k_init<<<(BATCH * HW + 255) / 256, 256>>>();
    k_prepA<<<BATCH * (CCH / 2), 256>>>(A);
    dim3 bgrid(HW / 256, CCH / 2, BATCH);
    k_prepB<<<bgrid, 256>>>(Bf);
    dim3 ggrid(HW / TN, HW / TM, BATCH);
    k_gemm_mma<<<ggrid, 256, SMEM_DYN>>>();
    dim3 sgrid(HW / 128, BATCH);
    k_stats<<<sgrid, 256>>>(out);
    k_norm<<<sgrid, 256>>>(out);
}